// round 3
// baseline (speedup 1.0000x reference)
#include <cuda_runtime.h>
#include <math.h>

#define BB 2
#define TT 2048
#define DD 1024
#define SS 32
#define CN 128
#define NCH 16
#define KT 8
#define ALPHA 0.05f
#define AVAL 0.95f
#define RSCALE 0.03125f
#define LNEPS 1e-5f

// scratch (device globals)
__device__ float g_hn [BB*TT*DD];
__device__ float g_q  [BB*TT*DD];
__device__ float g_v  [BB*TT*DD];
__device__ float g_w  [BB*TT*SS];
__device__ float g_U  [BB*NCH*SS*DD];
__device__ float g_Ms [BB*NCH*SS*DD];
__device__ float g_Pp [BB*NCH*KT*CN*CN];
__device__ float g_QMp[BB*NCH*KT*CN*SS];
__device__ float g_G  [BB*NCH*CN*CN];
__device__ float g_at [BB*NCH*CN*SS];

// ---------------- 1) LayerNorm --------------------------------------------
__global__ void __launch_bounds__(256) ln_kernel(const float* __restrict__ h,
                                                 const float* __restrict__ gamma,
                                                 const float* __restrict__ beta) {
    __shared__ float sx[DD];
    __shared__ float sred[256];
    const int row = blockIdx.x;
    const float* hr = h + (size_t)row * DD;
    const int tid = threadIdx.x;
    float lsum = 0.f;
    for (int i = tid; i < DD; i += 256) { float x = hr[i]; sx[i] = x; lsum += x; }
    sred[tid] = lsum; __syncthreads();
    #pragma unroll
    for (int s = 128; s > 0; s >>= 1) { if (tid < s) sred[tid] += sred[tid + s]; __syncthreads(); }
    const float mu = sred[0] * (1.0f / DD);
    __syncthreads();
    float lvar = 0.f;
    for (int i = tid; i < DD; i += 256) { float d = sx[i] - mu; lvar += d * d; }
    sred[tid] = lvar; __syncthreads();
    #pragma unroll
    for (int s = 128; s > 0; s >>= 1) { if (tid < s) sred[tid] += sred[tid + s]; __syncthreads(); }
    const float rstd = rsqrtf(sred[0] * (1.0f / DD) + LNEPS);
    float* o = g_hn + (size_t)row * DD;
    for (int i = tid; i < DD; i += 256)
        o[i] = (sx[i] - mu) * rstd * gamma[i] + beta[i];
}

// ---------------- 2) q/v projection GEMM (C = hn @ W^T + b) ----------------
__global__ void __launch_bounds__(256) gemm_qv_kernel(const float* __restrict__ Wq,
                                                      const float* __restrict__ bq,
                                                      const float* __restrict__ Wv,
                                                      const float* __restrict__ bv) {
    __shared__ float sA[128][33];
    __shared__ float sB[128][33];
    const int m0 = blockIdx.y * 128;
    const int n0 = blockIdx.x * 128;
    const float* W    = blockIdx.z ? Wv : Wq;
    const float* bias = blockIdx.z ? bv : bq;
    float* C          = blockIdx.z ? g_v : g_q;
    const int tid = threadIdx.x;
    const int ty = tid >> 4, tx = tid & 15;
    float acc[8][8];
    #pragma unroll
    for (int i = 0; i < 8; i++)
        #pragma unroll
        for (int j = 0; j < 8; j++) acc[i][j] = 0.f;
    for (int k0 = 0; k0 < DD; k0 += 32) {
        #pragma unroll
        for (int l = 0; l < 4; l++) {
            const int f4 = tid + l * 256;
            const int r  = f4 >> 3;
            const int kc = (f4 & 7) << 2;
            float4 a4 = *(const float4*)(&g_hn[(size_t)(m0 + r) * DD + k0 + kc]);
            sA[r][kc+0] = a4.x; sA[r][kc+1] = a4.y; sA[r][kc+2] = a4.z; sA[r][kc+3] = a4.w;
            float4 b4 = *(const float4*)(&W[(size_t)(n0 + r) * DD + k0 + kc]);
            sB[r][kc+0] = b4.x; sB[r][kc+1] = b4.y; sB[r][kc+2] = b4.z; sB[r][kc+3] = b4.w;
        }
        __syncthreads();
        #pragma unroll
        for (int kk = 0; kk < 32; kk++) {
            float ar[8], br[8];
            #pragma unroll
            for (int i = 0; i < 8; i++) ar[i] = sA[ty*8 + i][kk];
            #pragma unroll
            for (int j = 0; j < 8; j++) br[j] = sB[tx*8 + j][kk];
            #pragma unroll
            for (int i = 0; i < 8; i++)
                #pragma unroll
                for (int j = 0; j < 8; j++) acc[i][j] += ar[i] * br[j];
        }
        __syncthreads();
    }
    #pragma unroll
    for (int i = 0; i < 8; i++) {
        const int row = m0 + ty*8 + i;
        #pragma unroll
        for (int j = 0; j < 8; j++) {
            const int col = n0 + tx*8 + j;
            C[(size_t)row * DD + col] = acc[i][j] + bias[col];
        }
    }
}

// ---------------- 3) routing scores + softmax -> w --------------------------
__global__ void __launch_bounds__(256) route_kernel(const float* __restrict__ state0) {
    __shared__ float sQ[128][65];
    __shared__ float sS[32][65];
    const int c = blockIdx.x, b = blockIdx.y;
    const int tid = threadIdx.x;
    const int t  = tid >> 1;
    const int sh = (tid & 1) * 16;
    float acc[16];
    #pragma unroll
    for (int j = 0; j < 16; j++) acc[j] = 0.f;
    for (int k0 = 0; k0 < DD; k0 += 64) {
        #pragma unroll
        for (int l = 0; l < 8; l++) {
            const int f4 = tid + l * 256;
            const int r  = f4 >> 4;
            const int kc = (f4 & 15) << 2;
            float4 a4 = *(const float4*)(&g_q[(size_t)(b*TT + c*CN + r)*DD + k0 + kc]);
            sQ[r][kc+0] = a4.x; sQ[r][kc+1] = a4.y; sQ[r][kc+2] = a4.z; sQ[r][kc+3] = a4.w;
        }
        #pragma unroll
        for (int l = 0; l < 2; l++) {
            const int f4 = tid + l * 256;
            const int r  = f4 >> 4;
            const int kc = (f4 & 15) << 2;
            float4 s4 = *(const float4*)(&state0[(size_t)(b*SS + r)*DD + k0 + kc]);
            sS[r][kc+0] = s4.x; sS[r][kc+1] = s4.y; sS[r][kc+2] = s4.z; sS[r][kc+3] = s4.w;
        }
        __syncthreads();
        for (int k = 0; k < 64; k++) {
            const float qv = sQ[t][k];
            #pragma unroll
            for (int sj = 0; sj < 16; sj++) acc[sj] += qv * sS[sh + sj][k];
        }
        __syncthreads();
    }
    // stash scores in sQ (reused as [128][33] view), then per-token softmax
    float* sc = &sQ[0][0];
    #pragma unroll
    for (int sj = 0; sj < 16; sj++) sc[t*33 + sh + sj] = acc[sj] * RSCALE;
    __syncthreads();
    if (tid < 128) {
        float mx = -1e30f;
        #pragma unroll
        for (int s = 0; s < SS; s++) mx = fmaxf(mx, sc[tid*33 + s]);
        float ev[SS]; float sum = 0.f;
        #pragma unroll
        for (int s = 0; s < SS; s++) { ev[s] = expf(sc[tid*33 + s] - mx); sum += ev[s]; }
        const float inv = 1.f / sum;
        const int base = (b*TT + c*CN + tid)*SS;
        #pragma unroll
        for (int s = 0; s < SS; s++) g_w[base + s] = ev[s] * inv;
    }
}

// ---------------- 4) per-chunk update U = sum_tau alpha a^{127-tau} w⊗v ----
__global__ void __launch_bounds__(256) u_kernel() {
    __shared__ float sV[128*64];
    __shared__ float sPw[128];
    const int dt = blockIdx.x, c = blockIdx.y, b = blockIdx.z;
    const int tid = threadIdx.x;
    if (tid < 128) sPw[tid] = powf(AVAL, (float)tid);
    #pragma unroll
    for (int l = 0; l < 8; l++) {
        const int f4 = tid + l * 256;
        const int r  = f4 >> 4;
        const int kc = (f4 & 15) << 2;
        float4 v4 = *(const float4*)(&g_v[(size_t)(b*TT + c*CN + r)*DD + dt*64 + kc]);
        sV[r*64 + kc+0] = v4.x; sV[r*64 + kc+1] = v4.y; sV[r*64 + kc+2] = v4.z; sV[r*64 + kc+3] = v4.w;
    }
    __syncthreads();
    const int s  = tid & 31;
    const int d0 = (tid >> 5) << 3;
    float acc[8];
    #pragma unroll
    for (int j = 0; j < 8; j++) acc[j] = 0.f;
    const float* wrow = &g_w[(b*TT + c*CN)*SS + s];
    for (int tau = 0; tau < CN; tau++) {
        const float wd = ALPHA * sPw[127 - tau] * wrow[tau*SS];
        #pragma unroll
        for (int j = 0; j < 8; j++) acc[j] += wd * sV[tau*64 + d0 + j];
    }
    const int ob = ((b*NCH + c)*SS + s)*DD + dt*64 + d0;
    #pragma unroll
    for (int j = 0; j < 8; j++) g_U[ob + j] = acc[j];
}

// ---------------- 5) sequential chunk scan ---------------------------------
__global__ void __launch_bounds__(256) scan_kernel(const float* __restrict__ state0,
                                                   float* __restrict__ outF) {
    const int idx = blockIdx.x * 256 + threadIdx.x;
    const int b = idx / (SS*DD);
    const int sd = idx - b*SS*DD;
    float m = state0[idx];
    const float dc = powf(AVAL, (float)CN);
    #pragma unroll
    for (int c = 0; c < NCH; c++) {
        g_Ms[(b*NCH + c)*SS*DD + sd] = m;
        m = dc * m + g_U[(b*NCH + c)*SS*DD + sd];
    }
    outF[idx] = m;
}

// ---------------- 6) R1: split-K partials P=q@v^T, QM=q@Ms^T ---------------
#define R1_SMEM ((128*129*2 + 32*129)*4)
__global__ void __launch_bounds__(256) r1_kernel() {
    extern __shared__ float sm1[];
    float* sQ = sm1;
    float* sV = sQ + 128*129;
    float* sM = sV + 128*129;
    const int kt = blockIdx.x, c = blockIdx.y, b = blockIdx.z;
    const int tid = threadIdx.x;
    const int ty = tid >> 4, tx = tid & 15;
    #pragma unroll
    for (int l = 0; l < 16; l++) {
        const int f4 = tid + l * 256;
        const int r  = f4 >> 5;
        const int kc = (f4 & 31) << 2;
        float4 q4 = *(const float4*)(&g_q[(size_t)(b*TT + c*CN + r)*DD + kt*128 + kc]);
        sQ[r*129 + kc+0] = q4.x; sQ[r*129 + kc+1] = q4.y; sQ[r*129 + kc+2] = q4.z; sQ[r*129 + kc+3] = q4.w;
        float4 v4 = *(const float4*)(&g_v[(size_t)(b*TT + c*CN + r)*DD + kt*128 + kc]);
        sV[r*129 + kc+0] = v4.x; sV[r*129 + kc+1] = v4.y; sV[r*129 + kc+2] = v4.z; sV[r*129 + kc+3] = v4.w;
    }
    #pragma unroll
    for (int l = 0; l < 4; l++) {
        const int f4 = tid + l * 256;
        const int r  = f4 >> 5;
        const int kc = (f4 & 31) << 2;
        float4 m4 = *(const float4*)(&g_Ms[((b*NCH + c)*SS + r)*DD + kt*128 + kc]);
        sM[r*129 + kc+0] = m4.x; sM[r*129 + kc+1] = m4.y; sM[r*129 + kc+2] = m4.z; sM[r*129 + kc+3] = m4.w;
    }
    __syncthreads();
    float acc[8][8], qm[8][2];
    #pragma unroll
    for (int i = 0; i < 8; i++) {
        qm[i][0] = qm[i][1] = 0.f;
        #pragma unroll
        for (int j = 0; j < 8; j++) acc[i][j] = 0.f;
    }
    const float* qb = sQ + (ty*8)*129;
    const float* vb = sV + (tx*8)*129;
    const float* mb = sM + (tx*2)*129;
    for (int k = 0; k < 128; k++) {
        float ar[8], br[8];
        #pragma unroll
        for (int i = 0; i < 8; i++) ar[i] = qb[i*129 + k];
        #pragma unroll
        for (int j = 0; j < 8; j++) br[j] = vb[j*129 + k];
        const float m0 = mb[k], m1 = mb[129 + k];
        #pragma unroll
        for (int i = 0; i < 8; i++) {
            #pragma unroll
            for (int j = 0; j < 8; j++) acc[i][j] += ar[i] * br[j];
            qm[i][0] += ar[i] * m0;
            qm[i][1] += ar[i] * m1;
        }
    }
    const int pbase = (((b*NCH + c)*KT + kt)*CN + ty*8)*CN + tx*8;
    #pragma unroll
    for (int i = 0; i < 8; i++)
        #pragma unroll
        for (int j = 0; j < 8; j++) g_Pp[pbase + i*CN + j] = acc[i][j];
    const int qbase = (((b*NCH + c)*KT + kt)*CN + ty*8)*SS + tx*2;
    #pragma unroll
    for (int i = 0; i < 8; i++) {
        g_QMp[qbase + i*SS + 0] = qm[i][0];
        g_QMp[qbase + i*SS + 1] = qm[i][1];
    }
}

// ---------------- 7) R2: reduce, decay, scores, softmax, G ------------------
#define R2_SMEM ((128*129 + 128*33*2 + 132)*4)
__global__ void __launch_bounds__(256) r2_kernel() {
    extern __shared__ float sm2[];
    float* sP  = sm2;              // [128][129] decayed masked P
    float* sW  = sP + 128*129;     // [128][33]
    float* sA  = sW + 128*33;      // [128][33]
    float* sPw = sA + 128*33;      // [132]
    const int c = blockIdx.x, b = blockIdx.y;
    const int tid = threadIdx.x;
    if (tid < 132) sPw[tid] = powf(AVAL, (float)tid);
    __syncthreads();
    const int pbase = ((b*NCH + c)*KT)*CN*CN;
    for (int e = tid; e < CN*CN; e += 256) {
        float sum = 0.f;
        #pragma unroll
        for (int kt = 0; kt < KT; kt++) sum += g_Pp[pbase + kt*CN*CN + e];
        const int t = e >> 7, tau = e & 127;
        sP[t*129 + tau] = (tau <= t) ? ALPHA * sPw[t - tau] * sum : 0.f;
    }
    const int qbase = ((b*NCH + c)*KT)*CN*SS;
    for (int e = tid; e < CN*SS; e += 256) {
        float sum = 0.f;
        #pragma unroll
        for (int kt = 0; kt < KT; kt++) sum += g_QMp[qbase + kt*CN*SS + e];
        const int t = e >> 5, s = e & 31;
        sA[t*33 + s] = RSCALE * sPw[t + 1] * sum;
    }
    for (int e = tid; e < CN*SS; e += 256) {
        const int t = e >> 5, s = e & 31;
        sW[t*33 + s] = g_w[(b*TT + c*CN + t)*SS + s];
    }
    __syncthreads();
    { // scores += scale * (Pd @ w)
        const int t  = tid >> 1;
        const int s0 = (tid & 1) * 16;
        float r[16];
        #pragma unroll
        for (int sj = 0; sj < 16; sj++) r[sj] = 0.f;
        for (int tau = 0; tau <= t; tau++) {
            const float p = sP[t*129 + tau];
            #pragma unroll
            for (int sj = 0; sj < 16; sj++) r[sj] += p * sW[tau*33 + s0 + sj];
        }
        __syncthreads();
        #pragma unroll
        for (int sj = 0; sj < 16; sj++) sA[t*33 + s0 + sj] += RSCALE * r[sj];
    }
    __syncthreads();
    if (tid < 128) { // softmax per token, store a^{t+1}*attn
        const int t = tid;
        float mx = -1e30f;
        #pragma unroll
        for (int s = 0; s < SS; s++) mx = fmaxf(mx, sA[t*33 + s]);
        float ev[SS]; float sum = 0.f;
        #pragma unroll
        for (int s = 0; s < SS; s++) { ev[s] = expf(sA[t*33 + s] - mx); sum += ev[s]; }
        const float inv = 1.f / sum;
        const float pw = sPw[t + 1];
        const int ab = ((b*NCH + c)*CN + t)*SS;
        #pragma unroll
        for (int s = 0; s < SS; s++) {
            const float a = ev[s] * inv;
            sA[t*33 + s] = a;
            g_at[ab + s] = pw * a;
        }
    }
    __syncthreads();
    // G[t,tau] = mask * alpha * a^{t-tau} * (attn[t] . w[tau])
    const int ty = tid >> 4, tx = tid & 15;
    const int gbase = ((b*NCH + c)*CN)*CN;
    #pragma unroll
    for (int i = 0; i < 8; i++) {
        const int t = ty*8 + i;
        #pragma unroll
        for (int j = 0; j < 8; j++) {
            const int tau = tx*8 + j;
            float g = 0.f;
            if (tau <= t) {
                #pragma unroll
                for (int s = 0; s < SS; s++) g += sA[t*33 + s] * sW[tau*33 + s];
                g *= ALPHA * sPw[t - tau];
            }
            g_G[gbase + t*CN + tau] = g;
        }
    }
}

// ---------------- 8) R3: ctx = G@v + (a^{t+1}attn)@Ms -----------------------
#define R3_SMEM ((128*129*2 + 32*129 + 128*33)*4)
__global__ void __launch_bounds__(256) r3_kernel(float* __restrict__ outC) {
    extern __shared__ float sm3[];
    float* sG  = sm3;
    float* sV  = sG + 128*129;
    float* sM  = sV + 128*129;
    float* sAt = sM + 32*129;
    const int dt = blockIdx.x, c = blockIdx.y, b = blockIdx.z;
    const int tid = threadIdx.x;
    const int ty = tid >> 4, tx = tid & 15;
    #pragma unroll
    for (int l = 0; l < 16; l++) {
        const int f4 = tid + l * 256;
        const int r  = f4 >> 5;
        const int kc = (f4 & 31) << 2;
        float4 gg = *(const float4*)(&g_G[((b*NCH + c)*CN + r)*CN + kc]);
        sG[r*129 + kc+0] = gg.x; sG[r*129 + kc+1] = gg.y; sG[r*129 + kc+2] = gg.z; sG[r*129 + kc+3] = gg.w;
        float4 v4 = *(const float4*)(&g_v[(size_t)(b*TT + c*CN + r)*DD + dt*128 + kc]);
        sV[r*129 + kc+0] = v4.x; sV[r*129 + kc+1] = v4.y; sV[r*129 + kc+2] = v4.z; sV[r*129 + kc+3] = v4.w;
    }
    #pragma unroll
    for (int l = 0; l < 4; l++) {
        const int f4 = tid + l * 256;
        const int r  = f4 >> 5;
        const int kc = (f4 & 31) << 2;
        float4 m4 = *(const float4*)(&g_Ms[((b*NCH + c)*SS + r)*DD + dt*128 + kc]);
        sM[r*129 + kc+0] = m4.x; sM[r*129 + kc+1] = m4.y; sM[r*129 + kc+2] = m4.z; sM[r*129 + kc+3] = m4.w;
    }
    #pragma unroll
    for (int l = 0; l < 4; l++) {
        const int f4 = tid + l * 256;
        const int r  = f4 >> 3;
        const int sc = (f4 & 7) << 2;
        float4 a4 = *(const float4*)(&g_at[((b*NCH + c)*CN + r)*SS + sc]);
        sAt[r*33 + sc+0] = a4.x; sAt[r*33 + sc+1] = a4.y; sAt[r*33 + sc+2] = a4.z; sAt[r*33 + sc+3] = a4.w;
    }
    __syncthreads();
    float acc[8][8];
    #pragma unroll
    for (int i = 0; i < 8; i++)
        #pragma unroll
        for (int j = 0; j < 8; j++) acc[i][j] = 0.f;
    const float* gb = sG + (ty*8)*129;
    for (int tau = 0; tau < 128; tau++) {
        float ar[8], br[8];
        #pragma unroll
        for (int i = 0; i < 8; i++) ar[i] = gb[i*129 + tau];
        #pragma unroll
        for (int j = 0; j < 8; j++) br[j] = sV[tau*129 + tx*8 + j];
        #pragma unroll
        for (int i = 0; i < 8; i++)
            #pragma unroll
            for (int j = 0; j < 8; j++) acc[i][j] += ar[i] * br[j];
    }
    const float* ab = sAt + (ty*8)*33;
    for (int s = 0; s < SS; s++) {
        float ar[8], br[8];
        #pragma unroll
        for (int i = 0; i < 8; i++) ar[i] = ab[i*33 + s];
        #pragma unroll
        for (int j = 0; j < 8; j++) br[j] = sM[s*129 + tx*8 + j];
        #pragma unroll
        for (int i = 0; i < 8; i++)
            #pragma unroll
            for (int j = 0; j < 8; j++) acc[i][j] += ar[i] * br[j];
    }
    #pragma unroll
    for (int i = 0; i < 8; i++) {
        const int row = b*TT + c*CN + ty*8 + i;
        #pragma unroll
        for (int j = 0; j < 8; j++)
            outC[(size_t)row*DD + dt*128 + tx*8 + j] = acc[i][j];
    }
}

extern "C" void kernel_launch(void* const* d_in, const int* in_sizes, int n_in,
                              void* d_out, int out_size) {
    (void)in_sizes; (void)n_in; (void)out_size;
    const float* h      = (const float*)d_in[0];
    const float* state0 = (const float*)d_in[1];
    const float* gamma  = (const float*)d_in[2];
    const float* beta   = (const float*)d_in[3];
    const float* Wq     = (const float*)d_in[4];
    const float* bq     = (const float*)d_in[5];
    const float* Wv     = (const float*)d_in[6];
    const float* bv     = (const float*)d_in[7];
    float* out = (float*)d_out;
    float* outCtx   = out;
    float* outFinal = out + (size_t)BB*TT*DD;

    cudaFuncSetAttribute(r1_kernel, cudaFuncAttributeMaxDynamicSharedMemorySize, R1_SMEM);
    cudaFuncSetAttribute(r2_kernel, cudaFuncAttributeMaxDynamicSharedMemorySize, R2_SMEM);
    cudaFuncSetAttribute(r3_kernel, cudaFuncAttributeMaxDynamicSharedMemorySize, R3_SMEM);

    ln_kernel<<<BB*TT, 256>>>(h, gamma, beta);
    gemm_qv_kernel<<<dim3(DD/128, BB*TT/128, 2), 256>>>(Wq, bq, Wv, bv);
    route_kernel<<<dim3(NCH, BB), 256>>>(state0);
    u_kernel<<<dim3(16, NCH, BB), 256>>>();
    scan_kernel<<<BB*SS*DD/256, 256>>>(state0, outFinal);
    r1_kernel<<<dim3(KT, NCH, BB), 256, R1_SMEM>>>();
    r2_kernel<<<dim3(NCH, BB), 256, R2_SMEM>>>();
    r3_kernel<<<dim3(DD/128, NCH, BB), 256, R3_SMEM>>>(outCtx);
}

// round 6
// speedup vs baseline: 1.6950x; 1.6950x over previous
#include <cuda_runtime.h>
#include <cuda_bf16.h>
#include <math.h>
#include <stdint.h>

#define BB 2
#define TT 2048
#define DD 1024
#define SS 32
#define CN 128
#define NCH 16
#define KT 8
#define ALPHA 0.05f
#define AVAL 0.95f
#define RSCALE 0.03125f
#define LNEPS 1e-5f

// scratch (device globals)
__device__ __nv_bfloat16 g_hn_hi[BB*TT*DD];
__device__ __nv_bfloat16 g_hn_lo[BB*TT*DD];
__device__ __nv_bfloat16 g_W_hi [2*DD*DD];
__device__ __nv_bfloat16 g_W_lo [2*DD*DD];
__device__ float g_q  [BB*TT*DD];
__device__ float g_v  [BB*TT*DD];
__device__ float g_w  [BB*TT*SS];
__device__ float g_U  [BB*NCH*SS*DD];
__device__ float g_Ms [BB*NCH*SS*DD];
__device__ float g_Pp [BB*NCH*KT*CN*CN];
__device__ float g_QMp[BB*NCH*KT*CN*SS];
__device__ float g_G  [BB*NCH*CN*CN];
__device__ float g_at [BB*NCH*CN*SS];

// ---------------- helpers ----------------------------------------------------
__device__ __forceinline__ uint32_t smem_u32(const void* p) {
    uint32_t a;
    asm("{ .reg .u64 t; cvta.to.shared.u64 t, %1; cvt.u32.u64 %0, t; }" : "=r"(a) : "l"(p));
    return a;
}
#define LDMX4(r0, r1, r2, r3, addr) \
    asm volatile("ldmatrix.sync.aligned.m8n8.x4.shared.b16 {%0,%1,%2,%3}, [%4];" \
        : "=r"(r0), "=r"(r1), "=r"(r2), "=r"(r3) : "r"(addr))
#define MMA16816(d, a, b) \
    asm volatile("mma.sync.aligned.m16n8k16.row.col.f32.bf16.bf16.f32 " \
        "{%0,%1,%2,%3}, {%4,%5,%6,%7}, {%8,%9}, {%0,%1,%2,%3};" \
        : "+f"((d)[0]), "+f"((d)[1]), "+f"((d)[2]), "+f"((d)[3]) \
        : "r"((a)[0]), "r"((a)[1]), "r"((a)[2]), "r"((a)[3]), "r"((b)[0]), "r"((b)[1]))

// ---------------- 1) LayerNorm -> bf16 hi/lo --------------------------------
__global__ void __launch_bounds__(256) ln_kernel(const float* __restrict__ h,
                                                 const float* __restrict__ gamma,
                                                 const float* __restrict__ beta) {
    __shared__ float sx[DD];
    __shared__ float sred[256];
    const int row = blockIdx.x;
    const float* hr = h + (size_t)row * DD;
    const int tid = threadIdx.x;
    float lsum = 0.f;
    for (int i = tid; i < DD; i += 256) { float x = hr[i]; sx[i] = x; lsum += x; }
    sred[tid] = lsum; __syncthreads();
    #pragma unroll
    for (int s = 128; s > 0; s >>= 1) { if (tid < s) sred[tid] += sred[tid + s]; __syncthreads(); }
    const float mu = sred[0] * (1.0f / DD);
    __syncthreads();
    float lvar = 0.f;
    for (int i = tid; i < DD; i += 256) { float d = sx[i] - mu; lvar += d * d; }
    sred[tid] = lvar; __syncthreads();
    #pragma unroll
    for (int s = 128; s > 0; s >>= 1) { if (tid < s) sred[tid] += sred[tid + s]; __syncthreads(); }
    const float rstd = rsqrtf(sred[0] * (1.0f / DD) + LNEPS);
    __nv_bfloat16* ohi = g_hn_hi + (size_t)row * DD;
    __nv_bfloat16* olo = g_hn_lo + (size_t)row * DD;
    for (int i = tid; i < DD; i += 256) {
        float y = (sx[i] - mu) * rstd * gamma[i] + beta[i];
        __nv_bfloat16 hi = __float2bfloat16(y);
        ohi[i] = hi;
        olo[i] = __float2bfloat16(y - __bfloat162float(hi));
    }
}

// ---------------- 1b) W -> bf16 hi/lo ---------------------------------------
__global__ void __launch_bounds__(256) convw_kernel(const float* __restrict__ Wq,
                                                    const float* __restrict__ Wv) {
    const size_t base = ((size_t)blockIdx.x * 256 + threadIdx.x) * 4;
    const float* W = (base < (size_t)DD*DD) ? Wq : Wv;
    const size_t off = (base < (size_t)DD*DD) ? base : base - (size_t)DD*DD;
    float4 x = *(const float4*)(&W[off]);
    __nv_bfloat16 h0 = __float2bfloat16(x.x), h1 = __float2bfloat16(x.y);
    __nv_bfloat16 h2 = __float2bfloat16(x.z), h3 = __float2bfloat16(x.w);
    *(__nv_bfloat162*)(&g_W_hi[base + 0]) = __nv_bfloat162(h0, h1);
    *(__nv_bfloat162*)(&g_W_hi[base + 2]) = __nv_bfloat162(h2, h3);
    *(__nv_bfloat162*)(&g_W_lo[base + 0]) = __nv_bfloat162(
        __float2bfloat16(x.x - __bfloat162float(h0)), __float2bfloat16(x.y - __bfloat162float(h1)));
    *(__nv_bfloat162*)(&g_W_lo[base + 2]) = __nv_bfloat162(
        __float2bfloat16(x.z - __bfloat162float(h2)), __float2bfloat16(x.w - __bfloat162float(h3)));
}

// ---------------- 2) q/v projection via mma.sync bf16 (hi/lo split) ---------
// C[m,n] = hn[m,:] . W[n,:] + bias[n].  CTA tile 128x128, 8 warps (2x4),
// warp tile 64x32, K staged 64 wide. SMEM rows padded to 72 bf16.
#define TSTRIDE 72
#define TILE_B (128*TSTRIDE*2)
#define GEMM_SMEM (4*TILE_B)
__global__ void __launch_bounds__(256) gemm_tc_kernel(const float* __restrict__ bq,
                                                      const float* __restrict__ bv) {
    extern __shared__ char smc[];
    const int tid = threadIdx.x;
    const int wid = tid >> 5, lane = tid & 31;
    const int n0 = blockIdx.x * 128;
    const int m0 = blockIdx.y * 128;
    const int z  = blockIdx.z;
    const __nv_bfloat16* Whi = g_W_hi + (size_t)z * DD * DD;
    const __nv_bfloat16* Wlo = g_W_lo + (size_t)z * DD * DD;
    const int m_base = (wid >> 2) * 64;
    const int n_base = (wid & 3) * 32;

    const uint32_t sA_hi = smem_u32(smc);
    const uint32_t sA_lo = sA_hi + TILE_B;
    const uint32_t sB_hi = sA_lo + TILE_B;
    const uint32_t sB_lo = sB_hi + TILE_B;

    float acc[4][4][4];
    #pragma unroll
    for (int mi = 0; mi < 4; mi++)
        #pragma unroll
        for (int nj = 0; nj < 4; nj++)
            #pragma unroll
            for (int r = 0; r < 4; r++) acc[mi][nj][r] = 0.f;

    // ldmatrix per-lane address offsets (within a tile)
    const int a_rr = lane & 15;
    const int a_kk = (lane >> 4) * 8;
    const int b_g  = lane >> 3;
    const int b_rr = lane & 7;
    const int b_nofs = (b_g >> 1) * 8;
    const int b_kofs = (b_g & 1) * 8;

    for (int k0 = 0; k0 < DD; k0 += 64) {
        #pragma unroll
        for (int l = 0; l < 4; l++) {
            const int idx = tid + l * 256;
            const int r = idx >> 3, c8 = (idx & 7) * 8;
            const size_t ga = (size_t)(m0 + r) * DD + k0 + c8;
            const size_t gb = (size_t)(n0 + r) * DD + k0 + c8;
            const uint32_t so = (uint32_t)(r * TSTRIDE + c8) * 2;
            *(uint4*)(smc + 0*TILE_B + so) = *(const uint4*)(&g_hn_hi[ga]);
            *(uint4*)(smc + 1*TILE_B + so) = *(const uint4*)(&g_hn_lo[ga]);
            *(uint4*)(smc + 2*TILE_B + so) = *(const uint4*)(&Whi[gb]);
            *(uint4*)(smc + 3*TILE_B + so) = *(const uint4*)(&Wlo[gb]);
        }
        __syncthreads();

        #pragma unroll
        for (int ks = 0; ks < 4; ks++) {
            uint32_t ah[4][4], al[4][4];
            #pragma unroll
            for (int mi = 0; mi < 4; mi++) {
                const uint32_t off = (uint32_t)((m_base + mi*16 + a_rr) * TSTRIDE + ks*16 + a_kk) * 2;
                LDMX4(ah[mi][0], ah[mi][1], ah[mi][2], ah[mi][3], sA_hi + off);
                LDMX4(al[mi][0], al[mi][1], al[mi][2], al[mi][3], sA_lo + off);
            }
            uint32_t bh[4][2], bl[4][2];
            #pragma unroll
            for (int ni = 0; ni < 2; ni++) {
                const uint32_t off = (uint32_t)((n_base + ni*16 + b_nofs + b_rr) * TSTRIDE + ks*16 + b_kofs) * 2;
                LDMX4(bh[2*ni][0], bh[2*ni][1], bh[2*ni+1][0], bh[2*ni+1][1], sB_hi + off);
                LDMX4(bl[2*ni][0], bl[2*ni][1], bl[2*ni+1][0], bl[2*ni+1][1], sB_lo + off);
            }
            #pragma unroll
            for (int mi = 0; mi < 4; mi++)
                #pragma unroll
                for (int nj = 0; nj < 4; nj++) {
                    MMA16816(acc[mi][nj], ah[mi], bh[nj]);
                    MMA16816(acc[mi][nj], ah[mi], bl[nj]);
                    MMA16816(acc[mi][nj], al[mi], bh[nj]);
                }
        }
        __syncthreads();
    }

    float* C = z ? g_v : g_q;
    const float* bias = z ? bv : bq;
    #pragma unroll
    for (int mi = 0; mi < 4; mi++) {
        const int row0 = m0 + m_base + mi*16 + (lane >> 2);
        #pragma unroll
        for (int nj = 0; nj < 4; nj++) {
            const int col = n0 + n_base + nj*8 + (lane & 3) * 2;
            const float b0 = bias[col], b1 = bias[col + 1];
            float2 v0 = { acc[mi][nj][0] + b0, acc[mi][nj][1] + b1 };
            float2 v1 = { acc[mi][nj][2] + b0, acc[mi][nj][3] + b1 };
            *(float2*)(&C[(size_t)row0 * DD + col]) = v0;
            *(float2*)(&C[(size_t)(row0 + 8) * DD + col]) = v1;
        }
    }
}

// ---------------- 3) routing scores + softmax -> w --------------------------
__global__ void __launch_bounds__(256) route_kernel(const float* __restrict__ state0) {
    __shared__ float sQ[128][65];
    __shared__ float sS[32][65];
    const int c = blockIdx.x, b = blockIdx.y;
    const int tid = threadIdx.x;
    const int t  = tid >> 1;
    const int sh = (tid & 1) * 16;
    float acc[16];
    #pragma unroll
    for (int j = 0; j < 16; j++) acc[j] = 0.f;
    for (int k0 = 0; k0 < DD; k0 += 64) {
        #pragma unroll
        for (int l = 0; l < 8; l++) {
            const int f4 = tid + l * 256;
            const int r  = f4 >> 4;
            const int kc = (f4 & 15) << 2;
            float4 a4 = *(const float4*)(&g_q[(size_t)(b*TT + c*CN + r)*DD + k0 + kc]);
            sQ[r][kc+0] = a4.x; sQ[r][kc+1] = a4.y; sQ[r][kc+2] = a4.z; sQ[r][kc+3] = a4.w;
        }
        #pragma unroll
        for (int l = 0; l < 2; l++) {
            const int f4 = tid + l * 256;
            const int r  = f4 >> 4;
            const int kc = (f4 & 15) << 2;
            float4 s4 = *(const float4*)(&state0[(size_t)(b*SS + r)*DD + k0 + kc]);
            sS[r][kc+0] = s4.x; sS[r][kc+1] = s4.y; sS[r][kc+2] = s4.z; sS[r][kc+3] = s4.w;
        }
        __syncthreads();
        for (int k = 0; k < 64; k++) {
            const float qv = sQ[t][k];
            #pragma unroll
            for (int sj = 0; sj < 16; sj++) acc[sj] += qv * sS[sh + sj][k];
        }
        __syncthreads();
    }
    float* sc = &sQ[0][0];
    #pragma unroll
    for (int sj = 0; sj < 16; sj++) sc[t*33 + sh + sj] = acc[sj] * RSCALE;
    __syncthreads();
    if (tid < 128) {
        float mx = -1e30f;
        #pragma unroll
        for (int s = 0; s < SS; s++) mx = fmaxf(mx, sc[tid*33 + s]);
        float ev[SS]; float sum = 0.f;
        #pragma unroll
        for (int s = 0; s < SS; s++) { ev[s] = expf(sc[tid*33 + s] - mx); sum += ev[s]; }
        const float inv = 1.f / sum;
        const int base = (b*TT + c*CN + tid)*SS;
        #pragma unroll
        for (int s = 0; s < SS; s++) g_w[base + s] = ev[s] * inv;
    }
}

// ---------------- 4) per-chunk update U --------------------------------------
__global__ void __launch_bounds__(256) u_kernel() {
    __shared__ float sV[128*64];
    __shared__ float sPw[128];
    const int dt = blockIdx.x, c = blockIdx.y, b = blockIdx.z;
    const int tid = threadIdx.x;
    if (tid < 128) sPw[tid] = powf(AVAL, (float)tid);
    #pragma unroll
    for (int l = 0; l < 8; l++) {
        const int f4 = tid + l * 256;
        const int r  = f4 >> 4;
        const int kc = (f4 & 15) << 2;
        float4 v4 = *(const float4*)(&g_v[(size_t)(b*TT + c*CN + r)*DD + dt*64 + kc]);
        sV[r*64 + kc+0] = v4.x; sV[r*64 + kc+1] = v4.y; sV[r*64 + kc+2] = v4.z; sV[r*64 + kc+3] = v4.w;
    }
    __syncthreads();
    const int s  = tid & 31;
    const int d0 = (tid >> 5) << 3;
    float acc[8];
    #pragma unroll
    for (int j = 0; j < 8; j++) acc[j] = 0.f;
    const float* wrow = &g_w[(b*TT + c*CN)*SS + s];
    for (int tau = 0; tau < CN; tau++) {
        const float wd = ALPHA * sPw[127 - tau] * wrow[tau*SS];
        #pragma unroll
        for (int j = 0; j < 8; j++) acc[j] += wd * sV[tau*64 + d0 + j];
    }
    const int ob = ((b*NCH + c)*SS + s)*DD + dt*64 + d0;
    #pragma unroll
    for (int j = 0; j < 8; j++) g_U[ob + j] = acc[j];
}

// ---------------- 5) sequential chunk scan ----------------------------------
__global__ void __launch_bounds__(256) scan_kernel(const float* __restrict__ state0,
                                                   float* __restrict__ outF) {
    const int idx = blockIdx.x * 256 + threadIdx.x;
    const int b = idx / (SS*DD);
    const int sd = idx - b*SS*DD;
    float m = state0[idx];
    const float dc = powf(AVAL, (float)CN);
    #pragma unroll
    for (int c = 0; c < NCH; c++) {
        g_Ms[(b*NCH + c)*SS*DD + sd] = m;
        m = dc * m + g_U[(b*NCH + c)*SS*DD + sd];
    }
    outF[idx] = m;
}

// ---------------- 6) R1: split-K partials P=q@v^T, QM=q@Ms^T ----------------
#define R1_SMEM ((128*129*2 + 32*129)*4)
__global__ void __launch_bounds__(256) r1_kernel() {
    extern __shared__ float sm1[];
    float* sQ = sm1;
    float* sV = sQ + 128*129;
    float* sM = sV + 128*129;
    const int kt = blockIdx.x, c = blockIdx.y, b = blockIdx.z;
    const int tid = threadIdx.x;
    const int ty = tid >> 4, tx = tid & 15;
    #pragma unroll
    for (int l = 0; l < 16; l++) {
        const int f4 = tid + l * 256;
        const int r  = f4 >> 5;
        const int kc = (f4 & 31) << 2;
        float4 q4 = *(const float4*)(&g_q[(size_t)(b*TT + c*CN + r)*DD + kt*128 + kc]);
        sQ[r*129 + kc+0] = q4.x; sQ[r*129 + kc+1] = q4.y; sQ[r*129 + kc+2] = q4.z; sQ[r*129 + kc+3] = q4.w;
        float4 v4 = *(const float4*)(&g_v[(size_t)(b*TT + c*CN + r)*DD + kt*128 + kc]);
        sV[r*129 + kc+0] = v4.x; sV[r*129 + kc+1] = v4.y; sV[r*129 + kc+2] = v4.z; sV[r*129 + kc+3] = v4.w;
    }
    #pragma unroll
    for (int l = 0; l < 4; l++) {
        const int f4 = tid + l * 256;
        const int r  = f4 >> 5;
        const int kc = (f4 & 31) << 2;
        float4 m4 = *(const float4*)(&g_Ms[((b*NCH + c)*SS + r)*DD + kt*128 + kc]);
        sM[r*129 + kc+0] = m4.x; sM[r*129 + kc+1] = m4.y; sM[r*129 + kc+2] = m4.z; sM[r*129 + kc+3] = m4.w;
    }
    __syncthreads();
    float acc[8][8], qm[8][2];
    #pragma unroll
    for (int i = 0; i < 8; i++) {
        qm[i][0] = qm[i][1] = 0.f;
        #pragma unroll
        for (int j = 0; j < 8; j++) acc[i][j] = 0.f;
    }
    const float* qb = sQ + (ty*8)*129;
    const float* vb = sV + (tx*8)*129;
    const float* mb = sM + (tx*2)*129;
    for (int k = 0; k < 128; k++) {
        float ar[8], br[8];
        #pragma unroll
        for (int i = 0; i < 8; i++) ar[i] = qb[i*129 + k];
        #pragma unroll
        for (int j = 0; j < 8; j++) br[j] = vb[j*129 + k];
        const float m0 = mb[k], m1 = mb[129 + k];
        #pragma unroll
        for (int i = 0; i < 8; i++) {
            #pragma unroll
            for (int j = 0; j < 8; j++) acc[i][j] += ar[i] * br[j];
            qm[i][0] += ar[i] * m0;
            qm[i][1] += ar[i] * m1;
        }
    }
    const int pbase = (((b*NCH + c)*KT + kt)*CN + ty*8)*CN + tx*8;
    #pragma unroll
    for (int i = 0; i < 8; i++)
        #pragma unroll
        for (int j = 0; j < 8; j++) g_Pp[pbase + i*CN + j] = acc[i][j];
    const int qbase = (((b*NCH + c)*KT + kt)*CN + ty*8)*SS + tx*2;
    #pragma unroll
    for (int i = 0; i < 8; i++) {
        g_QMp[qbase + i*SS + 0] = qm[i][0];
        g_QMp[qbase + i*SS + 1] = qm[i][1];
    }
}

// ---------------- 7) R2: reduce, decay, scores, softmax, G ------------------
#define R2_SMEM ((128*129 + 128*33*2 + 132)*4)
__global__ void __launch_bounds__(256) r2_kernel() {
    extern __shared__ float sm2[];
    float* sP  = sm2;
    float* sW  = sP + 128*129;
    float* sA  = sW + 128*33;
    float* sPw = sA + 128*33;
    const int c = blockIdx.x, b = blockIdx.y;
    const int tid = threadIdx.x;
    if (tid < 132) sPw[tid] = powf(AVAL, (float)tid);
    __syncthreads();
    const int pbase = ((b*NCH + c)*KT)*CN*CN;
    for (int e = tid; e < CN*CN; e += 256) {
        float sum = 0.f;
        #pragma unroll
        for (int kt = 0; kt < KT; kt++) sum += g_Pp[pbase + kt*CN*CN + e];
        const int t = e >> 7, tau = e & 127;
        sP[t*129 + tau] = (tau <= t) ? ALPHA * sPw[t - tau] * sum : 0.f;
    }
    const int qbase = ((b*NCH + c)*KT)*CN*SS;
    for (int e = tid; e < CN*SS; e += 256) {
        float sum = 0.f;
        #pragma unroll
        for (int kt = 0; kt < KT; kt++) sum += g_QMp[qbase + kt*CN*SS + e];
        const int t = e >> 5, s = e & 31;
        sA[t*33 + s] = RSCALE * sPw[t + 1] * sum;
    }
    for (int e = tid; e < CN*SS; e += 256) {
        const int t = e >> 5, s = e & 31;
        sW[t*33 + s] = g_w[(b*TT + c*CN + t)*SS + s];
    }
    __syncthreads();
    {
        const int t  = tid >> 1;
        const int s0 = (tid & 1) * 16;
        float r[16];
        #pragma unroll
        for (int sj = 0; sj < 16; sj++) r[sj] = 0.f;
        for (int tau = 0; tau <= t; tau++) {
            const float p = sP[t*129 + tau];
            #pragma unroll
            for (int sj = 0; sj < 16; sj++) r[sj] += p * sW[tau*33 + s0 + sj];
        }
        __syncthreads();
        #pragma unroll
        for (int sj = 0; sj < 16; sj++) sA[t*33 + s0 + sj] += RSCALE * r[sj];
    }
    __syncthreads();
    if (tid < 128) {
        const int t = tid;
        float mx = -1e30f;
        #pragma unroll
        for (int s = 0; s < SS; s++) mx = fmaxf(mx, sA[t*33 + s]);
        float ev[SS]; float sum = 0.f;
        #pragma unroll
        for (int s = 0; s < SS; s++) { ev[s] = expf(sA[t*33 + s] - mx); sum += ev[s]; }
        const float inv = 1.f / sum;
        const float pw = sPw[t + 1];
        const int ab = ((b*NCH + c)*CN + t)*SS;
        #pragma unroll
        for (int s = 0; s < SS; s++) {
            const float a = ev[s] * inv;
            sA[t*33 + s] = a;
            g_at[ab + s] = pw * a;
        }
    }
    __syncthreads();
    const int ty = tid >> 4, tx = tid & 15;
    const int gbase = ((b*NCH + c)*CN)*CN;
    #pragma unroll
    for (int i = 0; i < 8; i++) {
        const int t = ty*8 + i;
        #pragma unroll
        for (int j = 0; j < 8; j++) {
            const int tau = tx*8 + j;
            float g = 0.f;
            if (tau <= t) {
                #pragma unroll
                for (int s = 0; s < SS; s++) g += sA[t*33 + s] * sW[tau*33 + s];
                g *= ALPHA * sPw[t - tau];
            }
            g_G[gbase + t*CN + tau] = g;
        }
    }
}

// ---------------- 8) R3: ctx = G@v + (a^{t+1}attn)@Ms -----------------------
#define R3_SMEM ((128*129*2 + 32*129 + 128*33)*4)
__global__ void __launch_bounds__(256) r3_kernel(float* __restrict__ outC) {
    extern __shared__ float sm3[];
    float* sG  = sm3;
    float* sV  = sG + 128*129;
    float* sM  = sV + 128*129;
    float* sAt = sM + 32*129;
    const int dt = blockIdx.x, c = blockIdx.y, b = blockIdx.z;
    const int tid = threadIdx.x;
    const int ty = tid >> 4, tx = tid & 15;
    #pragma unroll
    for (int l = 0; l < 16; l++) {
        const int f4 = tid + l * 256;
        const int r  = f4 >> 5;
        const int kc = (f4 & 31) << 2;
        float4 gg = *(const float4*)(&g_G[((b*NCH + c)*CN + r)*CN + kc]);
        sG[r*129 + kc+0] = gg.x; sG[r*129 + kc+1] = gg.y; sG[r*129 + kc+2] = gg.z; sG[r*129 + kc+3] = gg.w;
        float4 v4 = *(const float4*)(&g_v[(size_t)(b*TT + c*CN + r)*DD + dt*128 + kc]);
        sV[r*129 + kc+0] = v4.x; sV[r*129 + kc+1] = v4.y; sV[r*129 + kc+2] = v4.z; sV[r*129 + kc+3] = v4.w;
    }
    #pragma unroll
    for (int l = 0; l < 4; l++) {
        const int f4 = tid + l * 256;
        const int r  = f4 >> 5;
        const int kc = (f4 & 31) << 2;
        float4 m4 = *(const float4*)(&g_Ms[((b*NCH + c)*SS + r)*DD + dt*128 + kc]);
        sM[r*129 + kc+0] = m4.x; sM[r*129 + kc+1] = m4.y; sM[r*129 + kc+2] = m4.z; sM[r*129 + kc+3] = m4.w;
    }
    #pragma unroll
    for (int l = 0; l < 4; l++) {
        const int f4 = tid + l * 256;
        const int r  = f4 >> 3;
        const int sc = (f4 & 7) << 2;
        float4 a4 = *(const float4*)(&g_at[((b*NCH + c)*CN + r)*SS + sc]);
        sAt[r*33 + sc+0] = a4.x; sAt[r*33 + sc+1] = a4.y; sAt[r*33 + sc+2] = a4.z; sAt[r*33 + sc+3] = a4.w;
    }
    __syncthreads();
    float acc[8][8];
    #pragma unroll
    for (int i = 0; i < 8; i++)
        #pragma unroll
        for (int j = 0; j < 8; j++) acc[i][j] = 0.f;
    const float* gb = sG + (ty*8)*129;
    for (int tau = 0; tau < 128; tau++) {
        float ar[8], br[8];
        #pragma unroll
        for (int i = 0; i < 8; i++) ar[i] = gb[i*129 + tau];
        #pragma unroll
        for (int j = 0; j < 8; j++) br[j] = sV[tau*129 + tx*8 + j];
        #pragma unroll
        for (int i = 0; i < 8; i++)
            #pragma unroll
            for (int j = 0; j < 8; j++) acc[i][j] += ar[i] * br[j];
    }
    const float* ab = sAt + (ty*8)*33;
    for (int s = 0; s < SS; s++) {
        float ar[8], br[8];
        #pragma unroll
        for (int i = 0; i < 8; i++) ar[i] = ab[i*33 + s];
        #pragma unroll
        for (int j = 0; j < 8; j++) br[j] = sM[s*129 + tx*8 + j];
        #pragma unroll
        for (int i = 0; i < 8; i++)
            #pragma unroll
            for (int j = 0; j < 8; j++) acc[i][j] += ar[i] * br[j];
    }
    #pragma unroll
    for (int i = 0; i < 8; i++) {
        const int row = b*TT + c*CN + ty*8 + i;
        #pragma unroll
        for (int j = 0; j < 8; j++)
            outC[(size_t)row*DD + dt*128 + tx*8 + j] = acc[i][j];
    }
}

extern "C" void kernel_launch(void* const* d_in, const int* in_sizes, int n_in,
                              void* d_out, int out_size) {
    (void)in_sizes; (void)n_in; (void)out_size;
    const float* h      = (const float*)d_in[0];
    const float* state0 = (const float*)d_in[1];
    const float* gamma  = (const float*)d_in[2];
    const float* beta   = (const float*)d_in[3];
    const float* Wq     = (const float*)d_in[4];
    const float* bq     = (const float*)d_in[5];
    const float* Wv     = (const float*)d_in[6];
    const float* bv     = (const float*)d_in[7];
    float* out = (float*)d_out;
    float* outCtx   = out;
    float* outFinal = out + (size_t)BB*TT*DD;

    cudaFuncSetAttribute(gemm_tc_kernel, cudaFuncAttributeMaxDynamicSharedMemorySize, GEMM_SMEM);
    cudaFuncSetAttribute(r1_kernel, cudaFuncAttributeMaxDynamicSharedMemorySize, R1_SMEM);
    cudaFuncSetAttribute(r2_kernel, cudaFuncAttributeMaxDynamicSharedMemorySize, R2_SMEM);
    cudaFuncSetAttribute(r3_kernel, cudaFuncAttributeMaxDynamicSharedMemorySize, R3_SMEM);

    ln_kernel<<<BB*TT, 256>>>(h, gamma, beta);
    convw_kernel<<<2*DD*DD/1024, 256>>>(Wq, Wv);
    gemm_tc_kernel<<<dim3(DD/128, BB*TT/128, 2), 256, GEMM_SMEM>>>(bq, bv);
    route_kernel<<<dim3(NCH, BB), 256>>>(state0);
    u_kernel<<<dim3(16, NCH, BB), 256>>>();
    scan_kernel<<<BB*SS*DD/256, 256>>>(state0, outFinal);
    r1_kernel<<<dim3(KT, NCH, BB), 256, R1_SMEM>>>();
    r2_kernel<<<dim3(NCH, BB), 256, R2_SMEM>>>();
    r3_kernel<<<dim3(DD/128, NCH, BB), 256, R3_SMEM>>>(outCtx);
}

// round 7
// speedup vs baseline: 1.9143x; 1.1294x over previous
#include <cuda_runtime.h>
#include <cuda_bf16.h>
#include <math.h>
#include <stdint.h>

#define BB 2
#define TT 2048
#define DD 1024
#define SS 32
#define CN 128
#define NCH 16
#define KT 8
#define ALPHA 0.05f
#define AVAL 0.95f
#define RSCALE 0.03125f
#define LNEPS 1e-5f

// scratch (device globals)
__device__ __nv_bfloat16 g_hn_hi[BB*TT*DD];
__device__ __nv_bfloat16 g_hn_lo[BB*TT*DD];
__device__ __nv_bfloat16 g_W_hi [2*DD*DD];
__device__ __nv_bfloat16 g_W_lo [2*DD*DD];
__device__ float g_q  [BB*TT*DD];
__device__ float g_v  [BB*TT*DD];
__device__ float g_w  [BB*TT*SS];
__device__ float g_wsp[BB*NCH*8*CN*SS];
__device__ float g_U  [BB*NCH*SS*DD];
__device__ float g_Ms [BB*NCH*SS*DD];
__device__ float g_Pp [BB*NCH*KT*CN*CN];
__device__ float g_QMp[BB*NCH*KT*CN*SS];
__device__ float g_P  [BB*NCH*CN*CN];
__device__ float g_QM [BB*NCH*CN*SS];
__device__ float g_G  [BB*NCH*CN*CN];
__device__ float g_at [BB*NCH*CN*SS];

// ---------------- helpers ----------------------------------------------------
__device__ __forceinline__ uint32_t smem_u32(const void* p) {
    uint32_t a;
    asm("{ .reg .u64 t; cvta.to.shared.u64 t, %1; cvt.u32.u64 %0, t; }" : "=r"(a) : "l"(p));
    return a;
}
#define LDMX4(r0, r1, r2, r3, addr) \
    asm volatile("ldmatrix.sync.aligned.m8n8.x4.shared.b16 {%0,%1,%2,%3}, [%4];" \
        : "=r"(r0), "=r"(r1), "=r"(r2), "=r"(r3) : "r"(addr))
#define MMA16816(d, a, b) \
    asm volatile("mma.sync.aligned.m16n8k16.row.col.f32.bf16.bf16.f32 " \
        "{%0,%1,%2,%3}, {%4,%5,%6,%7}, {%8,%9}, {%0,%1,%2,%3};" \
        : "+f"((d)[0]), "+f"((d)[1]), "+f"((d)[2]), "+f"((d)[3]) \
        : "r"((a)[0]), "r"((a)[1]), "r"((a)[2]), "r"((a)[3]), "r"((b)[0]), "r"((b)[1]))

// ---------------- 1) LayerNorm -> bf16 hi/lo --------------------------------
__global__ void __launch_bounds__(256) ln_kernel(const float* __restrict__ h,
                                                 const float* __restrict__ gamma,
                                                 const float* __restrict__ beta) {
    __shared__ float sx[DD];
    __shared__ float sred[256];
    const int row = blockIdx.x;
    const float* hr = h + (size_t)row * DD;
    const int tid = threadIdx.x;
    float lsum = 0.f;
    for (int i = tid; i < DD; i += 256) { float x = hr[i]; sx[i] = x; lsum += x; }
    sred[tid] = lsum; __syncthreads();
    #pragma unroll
    for (int s = 128; s > 0; s >>= 1) { if (tid < s) sred[tid] += sred[tid + s]; __syncthreads(); }
    const float mu = sred[0] * (1.0f / DD);
    __syncthreads();
    float lvar = 0.f;
    for (int i = tid; i < DD; i += 256) { float d = sx[i] - mu; lvar += d * d; }
    sred[tid] = lvar; __syncthreads();
    #pragma unroll
    for (int s = 128; s > 0; s >>= 1) { if (tid < s) sred[tid] += sred[tid + s]; __syncthreads(); }
    const float rstd = rsqrtf(sred[0] * (1.0f / DD) + LNEPS);
    __nv_bfloat16* ohi = g_hn_hi + (size_t)row * DD;
    __nv_bfloat16* olo = g_hn_lo + (size_t)row * DD;
    for (int i = tid; i < DD; i += 256) {
        float y = (sx[i] - mu) * rstd * gamma[i] + beta[i];
        __nv_bfloat16 hi = __float2bfloat16(y);
        ohi[i] = hi;
        olo[i] = __float2bfloat16(y - __bfloat162float(hi));
    }
}

// ---------------- 1b) W -> bf16 hi/lo ---------------------------------------
__global__ void __launch_bounds__(256) convw_kernel(const float* __restrict__ Wq,
                                                    const float* __restrict__ Wv) {
    const size_t base = ((size_t)blockIdx.x * 256 + threadIdx.x) * 4;
    const float* W = (base < (size_t)DD*DD) ? Wq : Wv;
    const size_t off = (base < (size_t)DD*DD) ? base : base - (size_t)DD*DD;
    float4 x = *(const float4*)(&W[off]);
    __nv_bfloat16 h0 = __float2bfloat16(x.x), h1 = __float2bfloat16(x.y);
    __nv_bfloat16 h2 = __float2bfloat16(x.z), h3 = __float2bfloat16(x.w);
    *(__nv_bfloat162*)(&g_W_hi[base + 0]) = __nv_bfloat162(h0, h1);
    *(__nv_bfloat162*)(&g_W_hi[base + 2]) = __nv_bfloat162(h2, h3);
    *(__nv_bfloat162*)(&g_W_lo[base + 0]) = __nv_bfloat162(
        __float2bfloat16(x.x - __bfloat162float(h0)), __float2bfloat16(x.y - __bfloat162float(h1)));
    *(__nv_bfloat162*)(&g_W_lo[base + 2]) = __nv_bfloat162(
        __float2bfloat16(x.z - __bfloat162float(h2)), __float2bfloat16(x.w - __bfloat162float(h3)));
}

// ---------------- 2) q/v projection via mma.sync bf16 (hi/lo split) ---------
#define TSTRIDE 72
#define TILE_B (128*TSTRIDE*2)
#define GEMM_SMEM (4*TILE_B)
__global__ void __launch_bounds__(256) gemm_tc_kernel(const float* __restrict__ bq,
                                                      const float* __restrict__ bv) {
    extern __shared__ char smc[];
    const int tid = threadIdx.x;
    const int wid = tid >> 5, lane = tid & 31;
    const int n0 = blockIdx.x * 128;
    const int m0 = blockIdx.y * 128;
    const int z  = blockIdx.z;
    const __nv_bfloat16* Whi = g_W_hi + (size_t)z * DD * DD;
    const __nv_bfloat16* Wlo = g_W_lo + (size_t)z * DD * DD;
    const int m_base = (wid >> 2) * 64;
    const int n_base = (wid & 3) * 32;

    const uint32_t sA_hi = smem_u32(smc);
    const uint32_t sA_lo = sA_hi + TILE_B;
    const uint32_t sB_hi = sA_lo + TILE_B;
    const uint32_t sB_lo = sB_hi + TILE_B;

    float acc[4][4][4];
    #pragma unroll
    for (int mi = 0; mi < 4; mi++)
        #pragma unroll
        for (int nj = 0; nj < 4; nj++)
            #pragma unroll
            for (int r = 0; r < 4; r++) acc[mi][nj][r] = 0.f;

    const int a_rr = lane & 15;
    const int a_kk = (lane >> 4) * 8;
    const int b_g  = lane >> 3;
    const int b_rr = lane & 7;
    const int b_nofs = (b_g >> 1) * 8;
    const int b_kofs = (b_g & 1) * 8;

    for (int k0 = 0; k0 < DD; k0 += 64) {
        #pragma unroll
        for (int l = 0; l < 4; l++) {
            const int idx = tid + l * 256;
            const int r = idx >> 3, c8 = (idx & 7) * 8;
            const size_t ga = (size_t)(m0 + r) * DD + k0 + c8;
            const size_t gb = (size_t)(n0 + r) * DD + k0 + c8;
            const uint32_t so = (uint32_t)(r * TSTRIDE + c8) * 2;
            *(uint4*)(smc + 0*TILE_B + so) = *(const uint4*)(&g_hn_hi[ga]);
            *(uint4*)(smc + 1*TILE_B + so) = *(const uint4*)(&g_hn_lo[ga]);
            *(uint4*)(smc + 2*TILE_B + so) = *(const uint4*)(&Whi[gb]);
            *(uint4*)(smc + 3*TILE_B + so) = *(const uint4*)(&Wlo[gb]);
        }
        __syncthreads();

        #pragma unroll
        for (int ks = 0; ks < 4; ks++) {
            uint32_t ah[4][4], al[4][4];
            #pragma unroll
            for (int mi = 0; mi < 4; mi++) {
                const uint32_t off = (uint32_t)((m_base + mi*16 + a_rr) * TSTRIDE + ks*16 + a_kk) * 2;
                LDMX4(ah[mi][0], ah[mi][1], ah[mi][2], ah[mi][3], sA_hi + off);
                LDMX4(al[mi][0], al[mi][1], al[mi][2], al[mi][3], sA_lo + off);
            }
            uint32_t bh[4][2], bl[4][2];
            #pragma unroll
            for (int ni = 0; ni < 2; ni++) {
                const uint32_t off = (uint32_t)((n_base + ni*16 + b_nofs + b_rr) * TSTRIDE + ks*16 + b_kofs) * 2;
                LDMX4(bh[2*ni][0], bh[2*ni][1], bh[2*ni+1][0], bh[2*ni+1][1], sB_hi + off);
                LDMX4(bl[2*ni][0], bl[2*ni][1], bl[2*ni+1][0], bl[2*ni+1][1], sB_lo + off);
            }
            #pragma unroll
            for (int mi = 0; mi < 4; mi++)
                #pragma unroll
                for (int nj = 0; nj < 4; nj++) {
                    MMA16816(acc[mi][nj], ah[mi], bh[nj]);
                    MMA16816(acc[mi][nj], ah[mi], bl[nj]);
                    MMA16816(acc[mi][nj], al[mi], bh[nj]);
                }
        }
        __syncthreads();
    }

    float* C = z ? g_v : g_q;
    const float* bias = z ? bv : bq;
    #pragma unroll
    for (int mi = 0; mi < 4; mi++) {
        const int row0 = m0 + m_base + mi*16 + (lane >> 2);
        #pragma unroll
        for (int nj = 0; nj < 4; nj++) {
            const int col = n0 + n_base + nj*8 + (lane & 3) * 2;
            const float b0 = bias[col], b1 = bias[col + 1];
            float2 v0 = { acc[mi][nj][0] + b0, acc[mi][nj][1] + b1 };
            float2 v1 = { acc[mi][nj][2] + b0, acc[mi][nj][3] + b1 };
            *(float2*)(&C[(size_t)row0 * DD + col]) = v0;
            *(float2*)(&C[(size_t)(row0 + 8) * DD + col]) = v1;
        }
    }
}

// ---------------- 3a) routing score partials (split-K, 8 x 128) -------------
__global__ void __launch_bounds__(256) route_part_kernel(const float* __restrict__ state0) {
    __shared__ float sQ[128][65];
    __shared__ float sS[32][65];
    const int kt = blockIdx.x, c = blockIdx.y, b = blockIdx.z;
    const int tid = threadIdx.x;
    const int t  = tid >> 1;
    const int sh = (tid & 1) * 16;
    float acc[16];
    #pragma unroll
    for (int j = 0; j < 16; j++) acc[j] = 0.f;
    #pragma unroll
    for (int ki = 0; ki < 2; ki++) {
        const int k0 = kt * 128 + ki * 64;
        #pragma unroll
        for (int l = 0; l < 8; l++) {
            const int f4 = tid + l * 256;
            const int r  = f4 >> 4;
            const int kc = (f4 & 15) << 2;
            float4 a4 = *(const float4*)(&g_q[(size_t)(b*TT + c*CN + r)*DD + k0 + kc]);
            sQ[r][kc+0] = a4.x; sQ[r][kc+1] = a4.y; sQ[r][kc+2] = a4.z; sQ[r][kc+3] = a4.w;
        }
        #pragma unroll
        for (int l = 0; l < 2; l++) {
            const int f4 = tid + l * 256;
            const int r  = f4 >> 4;
            const int kc = (f4 & 15) << 2;
            float4 s4 = *(const float4*)(&state0[(size_t)(b*SS + r)*DD + k0 + kc]);
            sS[r][kc+0] = s4.x; sS[r][kc+1] = s4.y; sS[r][kc+2] = s4.z; sS[r][kc+3] = s4.w;
        }
        __syncthreads();
        for (int k = 0; k < 64; k++) {
            const float qv = sQ[t][k];
            #pragma unroll
            for (int sj = 0; sj < 16; sj++) acc[sj] += qv * sS[sh + sj][k];
        }
        __syncthreads();
    }
    const int base = ((b*NCH + c)*8 + kt)*CN*SS + t*SS + sh;
    #pragma unroll
    for (int sj = 0; sj < 16; sj++) g_wsp[base + sj] = acc[sj];
}

// ---------------- 3b) reduce partials + softmax -> w ------------------------
__global__ void __launch_bounds__(128) route_red_kernel() {
    const int c = blockIdx.x, b = blockIdx.y;
    const int t = threadIdx.x;
    const int base = ((b*NCH + c)*8)*CN*SS + t*SS;
    float sc[SS];
    #pragma unroll
    for (int s = 0; s < SS; s++) {
        float sum = 0.f;
        #pragma unroll
        for (int kt = 0; kt < 8; kt++) sum += g_wsp[base + kt*CN*SS + s];
        sc[s] = sum * RSCALE;
    }
    float mx = -1e30f;
    #pragma unroll
    for (int s = 0; s < SS; s++) mx = fmaxf(mx, sc[s]);
    float sum = 0.f;
    #pragma unroll
    for (int s = 0; s < SS; s++) { sc[s] = expf(sc[s] - mx); sum += sc[s]; }
    const float inv = 1.f / sum;
    const int ob = (b*TT + c*CN + t)*SS;
    #pragma unroll
    for (int s = 0; s < SS; s++) g_w[ob + s] = sc[s] * inv;
}

// ---------------- 4) per-chunk update U --------------------------------------
__global__ void __launch_bounds__(256) u_kernel() {
    __shared__ float sV[128*64];
    __shared__ float sPw[128];
    const int dt = blockIdx.x, c = blockIdx.y, b = blockIdx.z;
    const int tid = threadIdx.x;
    if (tid < 128) sPw[tid] = powf(AVAL, (float)tid);
    #pragma unroll
    for (int l = 0; l < 8; l++) {
        const int f4 = tid + l * 256;
        const int r  = f4 >> 4;
        const int kc = (f4 & 15) << 2;
        float4 v4 = *(const float4*)(&g_v[(size_t)(b*TT + c*CN + r)*DD + dt*64 + kc]);
        sV[r*64 + kc+0] = v4.x; sV[r*64 + kc+1] = v4.y; sV[r*64 + kc+2] = v4.z; sV[r*64 + kc+3] = v4.w;
    }
    __syncthreads();
    const int s  = tid & 31;
    const int d0 = (tid >> 5) << 3;
    float acc[8];
    #pragma unroll
    for (int j = 0; j < 8; j++) acc[j] = 0.f;
    const float* wrow = &g_w[(b*TT + c*CN)*SS + s];
    for (int tau = 0; tau < CN; tau++) {
        const float wd = ALPHA * sPw[127 - tau] * wrow[tau*SS];
        #pragma unroll
        for (int j = 0; j < 8; j++) acc[j] += wd * sV[tau*64 + d0 + j];
    }
    const int ob = ((b*NCH + c)*SS + s)*DD + dt*64 + d0;
    #pragma unroll
    for (int j = 0; j < 8; j++) g_U[ob + j] = acc[j];
}

// ---------------- 5) sequential chunk scan ----------------------------------
__global__ void __launch_bounds__(256) scan_kernel(const float* __restrict__ state0,
                                                   float* __restrict__ outF) {
    const int idx = blockIdx.x * 256 + threadIdx.x;
    const int b = idx / (SS*DD);
    const int sd = idx - b*SS*DD;
    float m = state0[idx];
    const float dc = powf(AVAL, (float)CN);
    #pragma unroll
    for (int c = 0; c < NCH; c++) {
        g_Ms[(b*NCH + c)*SS*DD + sd] = m;
        m = dc * m + g_U[(b*NCH + c)*SS*DD + sd];
    }
    outF[idx] = m;
}

// ---------------- 6) R1: split-K partials P=q@v^T, QM=q@Ms^T ----------------
#define R1_SMEM ((128*129*2 + 32*129)*4)
__global__ void __launch_bounds__(256) r1_kernel() {
    extern __shared__ float sm1[];
    float* sQ = sm1;
    float* sV = sQ + 128*129;
    float* sM = sV + 128*129;
    const int kt = blockIdx.x, c = blockIdx.y, b = blockIdx.z;
    const int tid = threadIdx.x;
    const int ty = tid >> 4, tx = tid & 15;
    #pragma unroll
    for (int l = 0; l < 16; l++) {
        const int f4 = tid + l * 256;
        const int r  = f4 >> 5;
        const int kc = (f4 & 31) << 2;
        float4 q4 = *(const float4*)(&g_q[(size_t)(b*TT + c*CN + r)*DD + kt*128 + kc]);
        sQ[r*129 + kc+0] = q4.x; sQ[r*129 + kc+1] = q4.y; sQ[r*129 + kc+2] = q4.z; sQ[r*129 + kc+3] = q4.w;
        float4 v4 = *(const float4*)(&g_v[(size_t)(b*TT + c*CN + r)*DD + kt*128 + kc]);
        sV[r*129 + kc+0] = v4.x; sV[r*129 + kc+1] = v4.y; sV[r*129 + kc+2] = v4.z; sV[r*129 + kc+3] = v4.w;
    }
    #pragma unroll
    for (int l = 0; l < 4; l++) {
        const int f4 = tid + l * 256;
        const int r  = f4 >> 5;
        const int kc = (f4 & 31) << 2;
        float4 m4 = *(const float4*)(&g_Ms[((b*NCH + c)*SS + r)*DD + kt*128 + kc]);
        sM[r*129 + kc+0] = m4.x; sM[r*129 + kc+1] = m4.y; sM[r*129 + kc+2] = m4.z; sM[r*129 + kc+3] = m4.w;
    }
    __syncthreads();
    float acc[8][8], qm[8][2];
    #pragma unroll
    for (int i = 0; i < 8; i++) {
        qm[i][0] = qm[i][1] = 0.f;
        #pragma unroll
        for (int j = 0; j < 8; j++) acc[i][j] = 0.f;
    }
    const float* qb = sQ + (ty*8)*129;
    const float* vb = sV + (tx*8)*129;
    const float* mb = sM + (tx*2)*129;
    for (int k = 0; k < 128; k++) {
        float ar[8], br[8];
        #pragma unroll
        for (int i = 0; i < 8; i++) ar[i] = qb[i*129 + k];
        #pragma unroll
        for (int j = 0; j < 8; j++) br[j] = vb[j*129 + k];
        const float m0 = mb[k], m1 = mb[129 + k];
        #pragma unroll
        for (int i = 0; i < 8; i++) {
            #pragma unroll
            for (int j = 0; j < 8; j++) acc[i][j] += ar[i] * br[j];
            qm[i][0] += ar[i] * m0;
            qm[i][1] += ar[i] * m1;
        }
    }
    const int pbase = (((b*NCH + c)*KT + kt)*CN + ty*8)*CN + tx*8;
    #pragma unroll
    for (int i = 0; i < 8; i++)
        #pragma unroll
        for (int j = 0; j < 8; j++) g_Pp[pbase + i*CN + j] = acc[i][j];
    const int qbase = (((b*NCH + c)*KT + kt)*CN + ty*8)*SS + tx*2;
    #pragma unroll
    for (int i = 0; i < 8; i++) {
        g_QMp[qbase + i*SS + 0] = qm[i][0];
        g_QMp[qbase + i*SS + 1] = qm[i][1];
    }
}

// ---------------- 6b) reduce split-K partials, apply decay/mask/scale -------
__global__ void __launch_bounds__(128) reduce_p_kernel() {
    const int t = blockIdx.x, c = blockIdx.y, b = blockIdx.z;
    const int tau = threadIdx.x;
    const int pb = ((b*NCH + c)*KT)*CN*CN + t*CN + tau;
    float sum = 0.f;
    #pragma unroll
    for (int kt = 0; kt < KT; kt++) sum += g_Pp[pb + kt*CN*CN];
    const float out = (tau <= t) ? ALPHA * powf(AVAL, (float)(t - tau)) * sum : 0.f;
    g_P[((b*NCH + c)*CN + t)*CN + tau] = out;
    if (tau < SS) {
        const int qb = ((b*NCH + c)*KT)*CN*SS + t*SS + tau;
        float s2 = 0.f;
        #pragma unroll
        for (int kt = 0; kt < KT; kt++) s2 += g_QMp[qb + kt*CN*SS];
        g_QM[((b*NCH + c)*CN + t)*SS + tau] = RSCALE * powf(AVAL, (float)(t + 1)) * s2;
    }
}

// ---------------- 7) R2: scores, softmax, G ---------------------------------
#define R2_SMEM ((128*129 + 128*33*2 + 132)*4)
__global__ void __launch_bounds__(256) r2_kernel() {
    extern __shared__ float sm2[];
    float* sP  = sm2;
    float* sW  = sP + 128*129;
    float* sA  = sW + 128*33;
    float* sPw = sA + 128*33;
    const int c = blockIdx.x, b = blockIdx.y;
    const int tid = threadIdx.x;
    if (tid < 132) sPw[tid] = powf(AVAL, (float)tid);
    __syncthreads();
    const int pbase = ((b*NCH + c)*CN)*CN;
    for (int e = tid; e < CN*CN; e += 256) {
        sP[(e >> 7)*129 + (e & 127)] = g_P[pbase + e];
    }
    const int qbase = ((b*NCH + c)*CN)*SS;
    for (int e = tid; e < CN*SS; e += 256) {
        sA[(e >> 5)*33 + (e & 31)] = g_QM[qbase + e];
    }
    for (int e = tid; e < CN*SS; e += 256) {
        const int t = e >> 5, s = e & 31;
        sW[t*33 + s] = g_w[(b*TT + c*CN + t)*SS + s];
    }
    __syncthreads();
    {
        const int t  = tid >> 1;
        const int s0 = (tid & 1) * 16;
        float r[16];
        #pragma unroll
        for (int sj = 0; sj < 16; sj++) r[sj] = 0.f;
        for (int tau = 0; tau <= t; tau++) {
            const float p = sP[t*129 + tau];
            #pragma unroll
            for (int sj = 0; sj < 16; sj++) r[sj] += p * sW[tau*33 + s0 + sj];
        }
        __syncthreads();
        #pragma unroll
        for (int sj = 0; sj < 16; sj++) sA[t*33 + s0 + sj] += RSCALE * r[sj];
    }
    __syncthreads();
    if (tid < 128) {
        const int t = tid;
        float mx = -1e30f;
        #pragma unroll
        for (int s = 0; s < SS; s++) mx = fmaxf(mx, sA[t*33 + s]);
        float ev[SS]; float sum = 0.f;
        #pragma unroll
        for (int s = 0; s < SS; s++) { ev[s] = expf(sA[t*33 + s] - mx); sum += ev[s]; }
        const float inv = 1.f / sum;
        const float pw = sPw[t + 1];
        const int ab = ((b*NCH + c)*CN + t)*SS;
        #pragma unroll
        for (int s = 0; s < SS; s++) {
            const float a = ev[s] * inv;
            sA[t*33 + s] = a;
            g_at[ab + s] = pw * a;
        }
    }
    __syncthreads();
    const int ty = tid >> 4, tx = tid & 15;
    const int gbase = ((b*NCH + c)*CN)*CN;
    #pragma unroll
    for (int i = 0; i < 8; i++) {
        const int t = ty*8 + i;
        #pragma unroll
        for (int j = 0; j < 8; j++) {
            const int tau = tx*8 + j;
            float g = 0.f;
            if (tau <= t) {
                #pragma unroll
                for (int s = 0; s < SS; s++) g += sA[t*33 + s] * sW[tau*33 + s];
                g *= ALPHA * sPw[t - tau];
            }
            g_G[gbase + t*CN + tau] = g;
        }
    }
}

// ---------------- 8) R3: ctx = G@v + (a^{t+1}attn)@Ms -----------------------
#define R3_SMEM ((128*129*2 + 32*129 + 128*33)*4)
__global__ void __launch_bounds__(256) r3_kernel(float* __restrict__ outC) {
    extern __shared__ float sm3[];
    float* sG  = sm3;
    float* sV  = sG + 128*129;
    float* sM  = sV + 128*129;
    float* sAt = sM + 32*129;
    const int dt = blockIdx.x, c = blockIdx.y, b = blockIdx.z;
    const int tid = threadIdx.x;
    const int ty = tid >> 4, tx = tid & 15;
    #pragma unroll
    for (int l = 0; l < 16; l++) {
        const int f4 = tid + l * 256;
        const int r  = f4 >> 5;
        const int kc = (f4 & 31) << 2;
        float4 gg = *(const float4*)(&g_G[((b*NCH + c)*CN + r)*CN + kc]);
        sG[r*129 + kc+0] = gg.x; sG[r*129 + kc+1] = gg.y; sG[r*129 + kc+2] = gg.z; sG[r*129 + kc+3] = gg.w;
        float4 v4 = *(const float4*)(&g_v[(size_t)(b*TT + c*CN + r)*DD + dt*128 + kc]);
        sV[r*129 + kc+0] = v4.x; sV[r*129 + kc+1] = v4.y; sV[r*129 + kc+2] = v4.z; sV[r*129 + kc+3] = v4.w;
    }
    #pragma unroll
    for (int l = 0; l < 4; l++) {
        const int f4 = tid + l * 256;
        const int r  = f4 >> 5;
        const int kc = (f4 & 31) << 2;
        float4 m4 = *(const float4*)(&g_Ms[((b*NCH + c)*SS + r)*DD + dt*128 + kc]);
        sM[r*129 + kc+0] = m4.x; sM[r*129 + kc+1] = m4.y; sM[r*129 + kc+2] = m4.z; sM[r*129 + kc+3] = m4.w;
    }
    #pragma unroll
    for (int l = 0; l < 4; l++) {
        const int f4 = tid + l * 256;
        const int r  = f4 >> 3;
        const int sc = (f4 & 7) << 2;
        float4 a4 = *(const float4*)(&g_at[((b*NCH + c)*CN + r)*SS + sc]);
        sAt[r*33 + sc+0] = a4.x; sAt[r*33 + sc+1] = a4.y; sAt[r*33 + sc+2] = a4.z; sAt[r*33 + sc+3] = a4.w;
    }
    __syncthreads();
    float acc[8][8];
    #pragma unroll
    for (int i = 0; i < 8; i++)
        #pragma unroll
        for (int j = 0; j < 8; j++) acc[i][j] = 0.f;
    const float* gb = sG + (ty*8)*129;
    for (int tau = 0; tau < 128; tau++) {
        float ar[8], br[8];
        #pragma unroll
        for (int i = 0; i < 8; i++) ar[i] = gb[i*129 + tau];
        #pragma unroll
        for (int j = 0; j < 8; j++) br[j] = sV[tau*129 + tx*8 + j];
        #pragma unroll
        for (int i = 0; i < 8; i++)
            #pragma unroll
            for (int j = 0; j < 8; j++) acc[i][j] += ar[i] * br[j];
    }
    const float* ab = sAt + (ty*8)*33;
    for (int s = 0; s < SS; s++) {
        float ar[8], br[8];
        #pragma unroll
        for (int i = 0; i < 8; i++) ar[i] = ab[i*33 + s];
        #pragma unroll
        for (int j = 0; j < 8; j++) br[j] = sM[s*129 + tx*8 + j];
        #pragma unroll
        for (int i = 0; i < 8; i++)
            #pragma unroll
            for (int j = 0; j < 8; j++) acc[i][j] += ar[i] * br[j];
    }
    #pragma unroll
    for (int i = 0; i < 8; i++) {
        const int row = b*TT + c*CN + ty*8 + i;
        #pragma unroll
        for (int j = 0; j < 8; j++)
            outC[(size_t)row*DD + dt*128 + tx*8 + j] = acc[i][j];
    }
}

extern "C" void kernel_launch(void* const* d_in, const int* in_sizes, int n_in,
                              void* d_out, int out_size) {
    (void)in_sizes; (void)n_in; (void)out_size;
    const float* h      = (const float*)d_in[0];
    const float* state0 = (const float*)d_in[1];
    const float* gamma  = (const float*)d_in[2];
    const float* beta   = (const float*)d_in[3];
    const float* Wq     = (const float*)d_in[4];
    const float* bq     = (const float*)d_in[5];
    const float* Wv     = (const float*)d_in[6];
    const float* bv     = (const float*)d_in[7];
    float* out = (float*)d_out;
    float* outCtx   = out;
    float* outFinal = out + (size_t)BB*TT*DD;

    cudaFuncSetAttribute(gemm_tc_kernel, cudaFuncAttributeMaxDynamicSharedMemorySize, GEMM_SMEM);
    cudaFuncSetAttribute(r1_kernel, cudaFuncAttributeMaxDynamicSharedMemorySize, R1_SMEM);
    cudaFuncSetAttribute(r2_kernel, cudaFuncAttributeMaxDynamicSharedMemorySize, R2_SMEM);
    cudaFuncSetAttribute(r3_kernel, cudaFuncAttributeMaxDynamicSharedMemorySize, R3_SMEM);

    ln_kernel<<<BB*TT, 256>>>(h, gamma, beta);
    convw_kernel<<<2*DD*DD/1024, 256>>>(Wq, Wv);
    gemm_tc_kernel<<<dim3(DD/128, BB*TT/128, 2), 256, GEMM_SMEM>>>(bq, bv);
    route_part_kernel<<<dim3(8, NCH, BB), 256>>>(state0);
    route_red_kernel<<<dim3(NCH, BB), 128>>>();
    u_kernel<<<dim3(16, NCH, BB), 256>>>();
    scan_kernel<<<BB*SS*DD/256, 256>>>(state0, outFinal);
    r1_kernel<<<dim3(KT, NCH, BB), 256, R1_SMEM>>>();
    reduce_p_kernel<<<dim3(CN, NCH, BB), 128>>>();
    r2_kernel<<<dim3(NCH, BB), 256, R2_SMEM>>>();
    r3_kernel<<<dim3(DD/128, NCH, BB), 256, R3_SMEM>>>(outCtx);
}